// round 5
// baseline (speedup 1.0000x reference)
#include <cuda_runtime.h>
#include <cuda_bf16.h>
#include <mma.h>
#include <cstdint>

using namespace nvcuda;

#define BSZ 128
#define TN  512
#define UN  1024
#define MROWS (TN * BSZ)   // 65536
#define NCTA 128           // persistent recurrence CTAs

// ---------------- scratch (static device globals) ----------------
__device__ __nv_bfloat16 g_Xhi[(size_t)MROWS * UN];
__device__ __nv_bfloat16 g_Xlo[(size_t)MROWS * UN];
__device__ __nv_bfloat16 g_Ehi[(size_t)MROWS * UN];
__device__ __nv_bfloat16 g_Elo[(size_t)MROWS * UN];
__device__ float         g_ZK [(size_t)MROWS * 4 * UN];   // permuted cols p=u*4+g
__device__ float         g_C  [(size_t)BSZ * UN];
__device__ __nv_bfloat16 g_Hhi[(size_t)(TN + 1) * BSZ * UN];
__device__ __nv_bfloat16 g_Hlo[(size_t)(TN + 1) * BSZ * UN];
__device__ __nv_bfloat16 g_Wemb_hi[(size_t)UN * UN];
__device__ __nv_bfloat16 g_Wemb_lo[(size_t)UN * UN];
__device__ __nv_bfloat16 g_Wout_hi[(size_t)UN * UN];
__device__ __nv_bfloat16 g_Wout_lo[(size_t)UN * UN];
__device__ __nv_bfloat16 g_Wk_hi[(size_t)UN * 4 * UN];    // permuted cols
__device__ __nv_bfloat16 g_Wk_lo[(size_t)UN * 4 * UN];
__device__ __nv_bfloat16 g_Wr_hi[(size_t)UN * 4 * UN];    // permuted cols
__device__ __nv_bfloat16 g_Wr_lo[(size_t)UN * 4 * UN];
__device__ int           g_count;                          // grid-barrier counter

struct __align__(8) BF4 { __nv_bfloat16 v[4]; };

__device__ __forceinline__ void bsplit(float v, __nv_bfloat16& h, __nv_bfloat16& l) {
    h = __float2bfloat16(v);
    l = __float2bfloat16(v - __bfloat162float(h));
}

// ---------------- prep kernels ----------------
__global__ void split_X(const float* __restrict__ X) {
    size_t i = (size_t)blockIdx.x * 256 + threadIdx.x;   // float4 index
    size_t e = i * 4;
    size_t r = e >> 10;
    int k = (int)(e & 1023);
    int b = (int)(r & 127), t = (int)(r >> 7);
    float4 v = *(const float4*)(X + ((size_t)b * 513 + (size_t)t) * 1024 + k);
    BF4 h, l;
    bsplit(v.x, h.v[0], l.v[0]); bsplit(v.y, h.v[1], l.v[1]);
    bsplit(v.z, h.v[2], l.v[2]); bsplit(v.w, h.v[3], l.v[3]);
    *(BF4*)(g_Xhi + e) = h;
    *(BF4*)(g_Xlo + e) = l;
}

__global__ void split_W(const float* __restrict__ W, __nv_bfloat16* __restrict__ hi,
                        __nv_bfloat16* __restrict__ lo, int N, int perm) {
    size_t i = (size_t)blockIdx.x * 256 + threadIdx.x;
    if (i >= (size_t)1024 * N) return;
    int col = (int)(i % N);
    size_t row = i / N;
    int sc = perm ? ((col & 3) * 1024 + (col >> 2)) : col;
    float v = W[row * N + sc];
    __nv_bfloat16 h, l; bsplit(v, h, l);
    hi[i] = h; lo[i] = l;
}

__global__ void init_state(const float* __restrict__ h0, const float* __restrict__ c0) {
    int i = blockIdx.x * 256 + threadIdx.x;
    if (i == 0) g_count = 0;
    if (i < BSZ * UN) {
        g_C[i] = c0[i];
        __nv_bfloat16 h, l; bsplit(h0[i], h, l);
        g_Hhi[i] = h; g_Hlo[i] = l;
    }
}

// ---------------- big bf16-split wmma GEMM ----------------
// mode 0: relu, split-write to (Dhi, Dlo) bf16
// mode 1: fp32 D, ldm N, bias read through unit-major permutation
// mode 2: fp32 D=d_out, row r=t*128+b scattered to [b][t][:]
__global__ __launch_bounds__(256) void wgemm(
    const __nv_bfloat16* __restrict__ Ahi, const __nv_bfloat16* __restrict__ Alo,
    const __nv_bfloat16* __restrict__ Bhi, const __nv_bfloat16* __restrict__ Blo,
    const float* __restrict__ bias, float* __restrict__ D,
    __nv_bfloat16* __restrict__ Dhi, __nv_bfloat16* __restrict__ Dlo,
    int N, int mode)
{
    __shared__ __nv_bfloat16 sAhi[128][40], sAlo[128][40];
    __shared__ __nv_bfloat16 sBhi[32][136], sBlo[32][136];
    __shared__ float sMulti[2048];   // sbias [16][128] overlay / stage [8][16][16]

    const int tid = threadIdx.x;
    const int n0 = blockIdx.x * 128, m0 = blockIdx.y * 128;
    const int wid = tid >> 5, lane = tid & 31;
    const int wm = wid & 3, wn = wid >> 2;

    float (*sbias)[128] = (float (*)[128])sMulti;
    for (int i = tid; i < 2048; i += 256) {
        int col = i & 127;
        int p = n0 + col;
        float bv = (mode == 1) ? bias[(p & 3) * 1024 + (p >> 2)] : bias[p];
        sbias[i >> 7][col] = bv;
    }
    __syncthreads();

    wmma::fragment<wmma::accumulator, 16, 16, 16, float> acc[2][4];
#pragma unroll
    for (int i = 0; i < 2; i++)
#pragma unroll
        for (int j = 0; j < 4; j++)
            wmma::load_matrix_sync(acc[i][j], &sbias[0][wn * 64 + j * 16], 128, wmma::mem_row_major);
    __syncthreads();

    const int ar0 = tid >> 2,          as_ = (tid & 3) * 8;
    const int ar1 = (tid + 256) >> 2;
    const int br0 = tid >> 4,          bs_ = (tid & 15) * 8;
    const int br1 = (tid + 256) >> 4;

    for (int k0 = 0; k0 < 1024; k0 += 32) {
        int4 a0h = *(const int4*)(Ahi + (size_t)(m0 + ar0) * 1024 + k0 + as_);
        int4 a1h = *(const int4*)(Ahi + (size_t)(m0 + ar1) * 1024 + k0 + as_);
        int4 a0l = *(const int4*)(Alo + (size_t)(m0 + ar0) * 1024 + k0 + as_);
        int4 a1l = *(const int4*)(Alo + (size_t)(m0 + ar1) * 1024 + k0 + as_);
        int4 b0h = *(const int4*)(Bhi + (size_t)(k0 + br0) * N + n0 + bs_);
        int4 b1h = *(const int4*)(Bhi + (size_t)(k0 + br1) * N + n0 + bs_);
        int4 b0l = *(const int4*)(Blo + (size_t)(k0 + br0) * N + n0 + bs_);
        int4 b1l = *(const int4*)(Blo + (size_t)(k0 + br1) * N + n0 + bs_);
        __syncthreads();
        *(int4*)&sAhi[ar0][as_] = a0h; *(int4*)&sAhi[ar1][as_] = a1h;
        *(int4*)&sAlo[ar0][as_] = a0l; *(int4*)&sAlo[ar1][as_] = a1l;
        *(int4*)&sBhi[br0][bs_] = b0h; *(int4*)&sBhi[br1][bs_] = b1h;
        *(int4*)&sBlo[br0][bs_] = b0l; *(int4*)&sBlo[br1][bs_] = b1l;
        __syncthreads();

#pragma unroll
        for (int kk = 0; kk < 32; kk += 16) {
            wmma::fragment<wmma::matrix_a, 16, 16, 16, __nv_bfloat16, wmma::row_major> ah[2], al[2];
            wmma::fragment<wmma::matrix_b, 16, 16, 16, __nv_bfloat16, wmma::row_major> bh[4], bl[4];
#pragma unroll
            for (int i = 0; i < 2; i++) {
                wmma::load_matrix_sync(ah[i], &sAhi[wm * 32 + i * 16][kk], 40);
                wmma::load_matrix_sync(al[i], &sAlo[wm * 32 + i * 16][kk], 40);
            }
#pragma unroll
            for (int j = 0; j < 4; j++) {
                wmma::load_matrix_sync(bh[j], &sBhi[kk][wn * 64 + j * 16], 136);
                wmma::load_matrix_sync(bl[j], &sBlo[kk][wn * 64 + j * 16], 136);
            }
#pragma unroll
            for (int i = 0; i < 2; i++)
#pragma unroll
                for (int j = 0; j < 4; j++) {
                    wmma::mma_sync(acc[i][j], ah[i], bh[j], acc[i][j]);
                    wmma::mma_sync(acc[i][j], ah[i], bl[j], acc[i][j]);
                    wmma::mma_sync(acc[i][j], al[i], bh[j], acc[i][j]);
                }
        }
    }

    if (mode == 0) {
        // relu + bf16 split, staged through smem per warp tile
        float (*stage)[16] = (float (*)[16])(sMulti + wid * 256);
        __syncthreads();
#pragma unroll
        for (int i = 0; i < 2; i++)
#pragma unroll
            for (int j = 0; j < 4; j++) {
                for (int e = 0; e < acc[i][j].num_elements; e++)
                    acc[i][j].x[e] = fmaxf(acc[i][j].x[e], 0.f);
                wmma::store_matrix_sync(&stage[0][0], acc[i][j], 16, wmma::mem_row_major);
                __syncwarp();
                int r = lane & 15, c8 = (lane >> 4) * 8;
                size_t row = (size_t)(m0 + wm * 32 + i * 16 + r);
                size_t off = row * 1024 + (n0 + wn * 64 + j * 16 + c8);
                BF4 h0v, l0v, h1v, l1v;
#pragma unroll
                for (int e = 0; e < 4; e++) bsplit(stage[r][c8 + e],     h0v.v[e], l0v.v[e]);
#pragma unroll
                for (int e = 0; e < 4; e++) bsplit(stage[r][c8 + 4 + e], h1v.v[e], l1v.v[e]);
                *(BF4*)(Dhi + off)     = h0v;
                *(BF4*)(Dlo + off)     = l0v;
                *(BF4*)(Dhi + off + 4) = h1v;
                *(BF4*)(Dlo + off + 4) = l1v;
                __syncwarp();
            }
        return;
    }

#pragma unroll
    for (int i = 0; i < 2; i++)
#pragma unroll
        for (int j = 0; j < 4; j++) {
            int col = n0 + wn * 64 + j * 16;
            if (mode == 2) {
                int t = m0 >> 7;
                int b = wm * 32 + i * 16;
                float* p = D + (size_t)t * 1024 + (size_t)b * ((size_t)TN * 1024) + col;
                wmma::store_matrix_sync(p, acc[i][j], (unsigned)(TN * 1024), wmma::mem_row_major);
            } else {
                int row = m0 + wm * 32 + i * 16;
                wmma::store_matrix_sync(D + (size_t)row * N + col, acc[i][j], N, wmma::mem_row_major);
            }
        }
}

// ---------------- persistent recurrence kernel ----------------
// 128 CTAs x 256 thr, all co-resident. CTA owns 32 permuted cols (8 units).
// SMEM: Whi [1024][32] 64K | Wlo 64K | A stages 2 x (Ahi[128][72] + Alo[128][72]) 72K
// z [128][36] fp32 overlays A-stage buf0.
#define SMP_WHI 0
#define SMP_WLO 65536
#define SMP_A   131072
#define SMP_ABUF 36864
#define SMP_TOTAL (131072 + 2 * SMP_ABUF)

__device__ __forceinline__ void cp16(uint32_t dst, const void* src) {
    asm volatile("cp.async.cg.shared.global [%0], [%1], 16;" :: "r"(dst), "l"(src));
}
__device__ __forceinline__ void cp_commit() { asm volatile("cp.async.commit_group;"); }
template<int N> __device__ __forceinline__ void cp_wait() {
    asm volatile("cp.async.wait_group %0;" :: "n"(N));
}

__global__ __launch_bounds__(256, 1) void lstm_persist(
    const __nv_bfloat16* __restrict__ Wh_g, const __nv_bfloat16* __restrict__ Wl_g)
{
    extern __shared__ char sm[];
    const uint32_t smb = (uint32_t)__cvta_generic_to_shared(sm);
    const int tid = threadIdx.x, wid = tid >> 5;
    const int bx = blockIdx.x;
    const int n0g = bx * 32;

    __nv_bfloat16 (*Wh)[32] = (__nv_bfloat16 (*)[32])(sm + SMP_WHI);
    __nv_bfloat16 (*Wl)[32] = (__nv_bfloat16 (*)[32])(sm + SMP_WLO);
    float (*z)[36] = (float (*)[36])(sm + SMP_A);

    // load W block once: [1024 k][32 cols] hi+lo
    for (int i = tid; i < 4096; i += 256) {
        int row = i >> 2;
        int seg = (i & 3) * 8;
        *(int4*)&Wh[row][seg] = *(const int4*)(Wh_g + (size_t)row * 4096 + n0g + seg);
        *(int4*)&Wl[row][seg] = *(const int4*)(Wl_g + (size_t)row * 4096 + n0g + seg);
    }
    __syncthreads();

    const int lrow = tid >> 3;           // 0..31
    const int lseg = (tid & 7) * 8;      // bf16 elems

    for (int t = 0; t < TN; t++) {
        const __nv_bfloat16* __restrict__ Hhi = g_Hhi + (size_t)t * (BSZ * UN);
        const __nv_bfloat16* __restrict__ Hlo = g_Hlo + (size_t)t * (BSZ * UN);

        wmma::fragment<wmma::accumulator, 16, 16, 16, float> acc[2];
        wmma::fill_fragment(acc[0], 0.f);
        wmma::fill_fragment(acc[1], 0.f);

        // prologue: chunk 0 -> buf 0
        {
            uint32_t ab = smb + SMP_A;
#pragma unroll
            for (int p = 0; p < 4; p++) {
                int row = p * 32 + lrow;
                cp16(ab + (row * 72 + lseg) * 2,         Hhi + (size_t)row * 1024 + lseg);
                cp16(ab + 18432 + (row * 72 + lseg) * 2, Hlo + (size_t)row * 1024 + lseg);
            }
            cp_commit();
        }

        for (int c = 0; c < 16; c++) {
            if (c < 15) {
                uint32_t ab = smb + SMP_A + ((c + 1) & 1) * SMP_ABUF;
                const __nv_bfloat16* hh = Hhi + (c + 1) * 64;
                const __nv_bfloat16* hl = Hlo + (c + 1) * 64;
#pragma unroll
                for (int p = 0; p < 4; p++) {
                    int row = p * 32 + lrow;
                    cp16(ab + (row * 72 + lseg) * 2,         hh + (size_t)row * 1024 + lseg);
                    cp16(ab + 18432 + (row * 72 + lseg) * 2, hl + (size_t)row * 1024 + lseg);
                }
                cp_commit();
                cp_wait<1>();
            } else {
                cp_wait<0>();
            }
            __syncthreads();

            __nv_bfloat16 (*Ahi)[72] = (__nv_bfloat16 (*)[72])(sm + SMP_A + (c & 1) * SMP_ABUF);
            __nv_bfloat16 (*Alo)[72] = (__nv_bfloat16 (*)[72])(sm + SMP_A + (c & 1) * SMP_ABUF + 18432);
#pragma unroll
            for (int sub = 0; sub < 4; sub++) {
                int kk = c * 64 + sub * 16;
                wmma::fragment<wmma::matrix_a, 16, 16, 16, __nv_bfloat16, wmma::row_major> ah, al;
                wmma::fragment<wmma::matrix_b, 16, 16, 16, __nv_bfloat16, wmma::row_major> bh0, bh1, bl0, bl1;
                wmma::load_matrix_sync(ah, &Ahi[wid * 16][sub * 16], 72);
                wmma::load_matrix_sync(al, &Alo[wid * 16][sub * 16], 72);
                wmma::load_matrix_sync(bh0, &Wh[kk][0],  32);
                wmma::load_matrix_sync(bh1, &Wh[kk][16], 32);
                wmma::load_matrix_sync(bl0, &Wl[kk][0],  32);
                wmma::load_matrix_sync(bl1, &Wl[kk][16], 32);
                wmma::mma_sync(acc[0], ah, bh0, acc[0]);
                wmma::mma_sync(acc[0], ah, bl0, acc[0]);
                wmma::mma_sync(acc[0], al, bh0, acc[0]);
                wmma::mma_sync(acc[1], ah, bh1, acc[1]);
                wmma::mma_sync(acc[1], ah, bl1, acc[1]);
                wmma::mma_sync(acc[1], al, bh1, acc[1]);
            }
            __syncthreads();
        }

        // stage z (overlays A buf0 — safe: loop finished, synced)
        wmma::store_matrix_sync(&z[wid * 16][0],  acc[0], 36, wmma::mem_row_major);
        wmma::store_matrix_sync(&z[wid * 16][16], acc[1], 36, wmma::mem_row_major);
        __syncthreads();

        // gate epilogue: thread -> row m = tid&127, half = tid>>7 -> 4 units (16 perm cols)
        {
            const int m = tid & 127;
            const int half = tid >> 7;
            const int pc = half * 16;
            const float* __restrict__ zk = g_ZK + ((size_t)t * BSZ + m) * 4096 + n0g + pc;
            float zkf[16];
#pragma unroll
            for (int q = 0; q < 4; q++) {
                float4 v = *(const float4*)(zk + q * 4);
                zkf[q * 4 + 0] = v.x; zkf[q * 4 + 1] = v.y;
                zkf[q * 4 + 2] = v.z; zkf[q * 4 + 3] = v.w;
            }
            float* __restrict__ cp = g_C + (size_t)m * UN + bx * 8 + half * 4;
            float4 cv4 = *(const float4*)cp;
            float cv[4] = {cv4.x, cv4.y, cv4.z, cv4.w};
            BF4 hh, hl;
#pragma unroll
            for (int e = 0; e < 4; e++) {
                float zi = z[m][pc + e * 4 + 0] + zkf[e * 4 + 0];
                float zf = z[m][pc + e * 4 + 1] + zkf[e * 4 + 1];
                float zg = z[m][pc + e * 4 + 2] + zkf[e * 4 + 2];
                float zo = z[m][pc + e * 4 + 3] + zkf[e * 4 + 3];
                float si = 1.f / (1.f + __expf(-zi));
                float sf = 1.f / (1.f + __expf(-zf));
                float so = 1.f / (1.f + __expf(-zo));
                float cn = sf * cv[e] + si * tanhf(zg);
                float hn = so * tanhf(cn);
                cv[e] = cn;
                bsplit(hn, hh.v[e], hl.v[e]);
            }
            *(float4*)cp = make_float4(cv[0], cv[1], cv[2], cv[3]);
            size_t ho = (size_t)(t + 1) * (BSZ * UN) + (size_t)m * UN + bx * 8 + half * 4;
            *(BF4*)(g_Hhi + ho) = hh;
            *(BF4*)(g_Hlo + ho) = hl;
        }

        // grid barrier
        __threadfence();
        __syncthreads();
        if (tid == 0) {
            atomicAdd(&g_count, 1);
            volatile int* gc = &g_count;
            int target = NCTA * (t + 1);
            while (*gc < target) __nanosleep(64);
        }
        __syncthreads();
    }
}

// ---------------- host ----------------
extern "C" void kernel_launch(void* const* d_in, const int* in_sizes, int n_in,
                              void* d_out, int out_size)
{
    const float* h0    = (const float*)d_in[0];
    const float* c0    = (const float*)d_in[1];
    const float* X     = (const float*)d_in[2];
    const float* W_emb = (const float*)d_in[3];
    const float* b_emb = (const float*)d_in[4];
    const float* W_k   = (const float*)d_in[5];
    const float* W_r   = (const float*)d_in[6];
    const float* b_r   = (const float*)d_in[7];
    const float* W_out = (const float*)d_in[8];
    const float* b_out = (const float*)d_in[9];
    (void)in_sizes; (void)n_in; (void)out_size;

    __nv_bfloat16 *pXhi, *pXlo, *pEhi, *pElo, *pHhi, *pHlo;
    __nv_bfloat16 *pWembh, *pWembl, *pWouth, *pWoutl, *pWkh, *pWkl, *pWrh, *pWrl;
    float *pZK;
    cudaGetSymbolAddress((void**)&pXhi, g_Xhi);
    cudaGetSymbolAddress((void**)&pXlo, g_Xlo);
    cudaGetSymbolAddress((void**)&pEhi, g_Ehi);
    cudaGetSymbolAddress((void**)&pElo, g_Elo);
    cudaGetSymbolAddress((void**)&pHhi, g_Hhi);
    cudaGetSymbolAddress((void**)&pHlo, g_Hlo);
    cudaGetSymbolAddress((void**)&pWembh, g_Wemb_hi);
    cudaGetSymbolAddress((void**)&pWembl, g_Wemb_lo);
    cudaGetSymbolAddress((void**)&pWouth, g_Wout_hi);
    cudaGetSymbolAddress((void**)&pWoutl, g_Wout_lo);
    cudaGetSymbolAddress((void**)&pWkh, g_Wk_hi);
    cudaGetSymbolAddress((void**)&pWkl, g_Wk_lo);
    cudaGetSymbolAddress((void**)&pWrh, g_Wr_hi);
    cudaGetSymbolAddress((void**)&pWrl, g_Wr_lo);
    cudaGetSymbolAddress((void**)&pZK, g_ZK);

    cudaFuncSetAttribute(lstm_persist, cudaFuncAttributeMaxDynamicSharedMemorySize, SMP_TOTAL);

    init_state<<<(BSZ * UN + 255) / 256, 256>>>(h0, c0);
    split_X<<<(int)((size_t)MROWS * UN / 4 / 256), 256>>>(X);
    split_W<<<(1024 * 1024 + 255) / 256, 256>>>(W_emb, pWembh, pWembl, 1024, 0);
    split_W<<<(1024 * 1024 + 255) / 256, 256>>>(W_out, pWouth, pWoutl, 1024, 0);
    split_W<<<(1024 * 4096 + 255) / 256, 256>>>(W_k, pWkh, pWkl, 4096, 1);
    split_W<<<(1024 * 4096 + 255) / 256, 256>>>(W_r, pWrh, pWrl, 4096, 1);

    {   // E = relu(X @ W_emb + b_emb), bf16 split written directly
        dim3 grid(1024 / 128, MROWS / 128);
        wgemm<<<grid, 256>>>(pXhi, pXlo, pWembh, pWembl, b_emb,
                             nullptr, pEhi, pElo, 1024, 0);
    }
    {   // ZK = E @ W_k + b_r (unit-major permuted columns)
        dim3 grid(4096 / 128, MROWS / 128);
        wgemm<<<grid, 256>>>(pEhi, pElo, pWkh, pWkl, b_r,
                             pZK, nullptr, nullptr, 4096, 1);
    }

    // recurrence: one persistent kernel, 512 steps, software grid barrier
    lstm_persist<<<NCTA, 256, SMP_TOTAL>>>(pWrh, pWrl);

    {   // OUT = H @ W_out + b_out, scattered to [b][t][:]
        dim3 grid(1024 / 128, MROWS / 128);
        wgemm<<<grid, 256>>>(pHhi + (size_t)BSZ * UN, pHlo + (size_t)BSZ * UN,
                             pWouth, pWoutl, b_out,
                             (float*)d_out, nullptr, nullptr, 1024, 2);
    }
}

// round 6
// speedup vs baseline: 1.0925x; 1.0925x over previous
#include <cuda_runtime.h>
#include <cuda_bf16.h>
#include <mma.h>
#include <cstdint>

using namespace nvcuda;

#define BSZ 128
#define TN  512
#define UN  1024
#define MROWS (TN * BSZ)   // 65536

// ---------------- scratch (static device globals) ----------------
__device__ __nv_bfloat16 g_Xhi[(size_t)MROWS * UN];
__device__ __nv_bfloat16 g_Xlo[(size_t)MROWS * UN];
__device__ __nv_bfloat16 g_Ehi[(size_t)MROWS * UN];
__device__ __nv_bfloat16 g_Elo[(size_t)MROWS * UN];
__device__ float         g_ZK [(size_t)MROWS * 4 * UN];   // permuted cols p=u*4+g
__device__ float         g_C  [(size_t)BSZ * UN];
__device__ __nv_bfloat16 g_Hhi[(size_t)(TN + 1) * BSZ * UN];
__device__ __nv_bfloat16 g_Hlo[(size_t)(TN + 1) * BSZ * UN];
__device__ __nv_bfloat16 g_Wemb_hi[(size_t)UN * UN];
__device__ __nv_bfloat16 g_Wemb_lo[(size_t)UN * UN];
__device__ __nv_bfloat16 g_Wout_hi[(size_t)UN * UN];
__device__ __nv_bfloat16 g_Wout_lo[(size_t)UN * UN];
__device__ __nv_bfloat16 g_Wk_hi[(size_t)UN * 4 * UN];    // permuted cols
__device__ __nv_bfloat16 g_Wk_lo[(size_t)UN * 4 * UN];
__device__ __nv_bfloat16 g_Wr_hi[(size_t)UN * 4 * UN];    // permuted cols
__device__ __nv_bfloat16 g_Wr_lo[(size_t)UN * 4 * UN];

struct __align__(8) BF4 { __nv_bfloat16 v[4]; };

__device__ __forceinline__ void bsplit(float v, __nv_bfloat16& h, __nv_bfloat16& l) {
    h = __float2bfloat16(v);
    l = __float2bfloat16(v - __bfloat162float(h));
}

// ---------------- prep kernels ----------------
__global__ void split_X(const float* __restrict__ X) {
    size_t i = (size_t)blockIdx.x * 256 + threadIdx.x;   // float4 index
    size_t e = i * 4;
    size_t r = e >> 10;
    int k = (int)(e & 1023);
    int b = (int)(r & 127), t = (int)(r >> 7);
    float4 v = *(const float4*)(X + ((size_t)b * 513 + (size_t)t) * 1024 + k);
    BF4 h, l;
    bsplit(v.x, h.v[0], l.v[0]); bsplit(v.y, h.v[1], l.v[1]);
    bsplit(v.z, h.v[2], l.v[2]); bsplit(v.w, h.v[3], l.v[3]);
    *(BF4*)(g_Xhi + e) = h;
    *(BF4*)(g_Xlo + e) = l;
}

__global__ void split_W(const float* __restrict__ W, __nv_bfloat16* __restrict__ hi,
                        __nv_bfloat16* __restrict__ lo, int N, int perm) {
    size_t i = (size_t)blockIdx.x * 256 + threadIdx.x;
    if (i >= (size_t)1024 * N) return;
    int col = (int)(i % N);
    size_t row = i / N;
    int sc = perm ? ((col & 3) * 1024 + (col >> 2)) : col;
    float v = W[row * N + sc];
    __nv_bfloat16 h, l; bsplit(v, h, l);
    hi[i] = h; lo[i] = l;
}

__global__ void init_state(const float* __restrict__ h0, const float* __restrict__ c0) {
    int i = blockIdx.x * 256 + threadIdx.x;
    if (i < BSZ * UN) {
        g_C[i] = c0[i];
        __nv_bfloat16 h, l; bsplit(h0[i], h, l);
        g_Hhi[i] = h; g_Hlo[i] = l;
    }
}

// ---------------- big bf16-split wmma GEMM ----------------
// mode 0: relu, split-write to (Dhi, Dlo) bf16
// mode 1: fp32 D, ldm N, bias read through unit-major permutation
// mode 2: fp32 D=d_out, row r=t*128+b scattered to [b][t][:]
__global__ __launch_bounds__(256) void wgemm(
    const __nv_bfloat16* __restrict__ Ahi, const __nv_bfloat16* __restrict__ Alo,
    const __nv_bfloat16* __restrict__ Bhi, const __nv_bfloat16* __restrict__ Blo,
    const float* __restrict__ bias, float* __restrict__ D,
    __nv_bfloat16* __restrict__ Dhi, __nv_bfloat16* __restrict__ Dlo,
    int N, int mode)
{
    __shared__ __nv_bfloat16 sAhi[128][40], sAlo[128][40];
    __shared__ __nv_bfloat16 sBhi[32][136], sBlo[32][136];
    __shared__ float sMulti[2048];

    const int tid = threadIdx.x;
    const int n0 = blockIdx.x * 128, m0 = blockIdx.y * 128;
    const int wid = tid >> 5, lane = tid & 31;
    const int wm = wid & 3, wn = wid >> 2;

    float (*sbias)[128] = (float (*)[128])sMulti;
    for (int i = tid; i < 2048; i += 256) {
        int col = i & 127;
        int p = n0 + col;
        float bv = (mode == 1) ? bias[(p & 3) * 1024 + (p >> 2)] : bias[p];
        sbias[i >> 7][col] = bv;
    }
    __syncthreads();

    wmma::fragment<wmma::accumulator, 16, 16, 16, float> acc[2][4];
#pragma unroll
    for (int i = 0; i < 2; i++)
#pragma unroll
        for (int j = 0; j < 4; j++)
            wmma::load_matrix_sync(acc[i][j], &sbias[0][wn * 64 + j * 16], 128, wmma::mem_row_major);
    __syncthreads();

    const int ar0 = tid >> 2,          as_ = (tid & 3) * 8;
    const int ar1 = (tid + 256) >> 2;
    const int br0 = tid >> 4,          bs_ = (tid & 15) * 8;
    const int br1 = (tid + 256) >> 4;

    for (int k0 = 0; k0 < 1024; k0 += 32) {
        int4 a0h = *(const int4*)(Ahi + (size_t)(m0 + ar0) * 1024 + k0 + as_);
        int4 a1h = *(const int4*)(Ahi + (size_t)(m0 + ar1) * 1024 + k0 + as_);
        int4 a0l = *(const int4*)(Alo + (size_t)(m0 + ar0) * 1024 + k0 + as_);
        int4 a1l = *(const int4*)(Alo + (size_t)(m0 + ar1) * 1024 + k0 + as_);
        int4 b0h = *(const int4*)(Bhi + (size_t)(k0 + br0) * N + n0 + bs_);
        int4 b1h = *(const int4*)(Bhi + (size_t)(k0 + br1) * N + n0 + bs_);
        int4 b0l = *(const int4*)(Blo + (size_t)(k0 + br0) * N + n0 + bs_);
        int4 b1l = *(const int4*)(Blo + (size_t)(k0 + br1) * N + n0 + bs_);
        __syncthreads();
        *(int4*)&sAhi[ar0][as_] = a0h; *(int4*)&sAhi[ar1][as_] = a1h;
        *(int4*)&sAlo[ar0][as_] = a0l; *(int4*)&sAlo[ar1][as_] = a1l;
        *(int4*)&sBhi[br0][bs_] = b0h; *(int4*)&sBhi[br1][bs_] = b1h;
        *(int4*)&sBlo[br0][bs_] = b0l; *(int4*)&sBlo[br1][bs_] = b1l;
        __syncthreads();

#pragma unroll
        for (int kk = 0; kk < 32; kk += 16) {
            wmma::fragment<wmma::matrix_a, 16, 16, 16, __nv_bfloat16, wmma::row_major> ah[2], al[2];
            wmma::fragment<wmma::matrix_b, 16, 16, 16, __nv_bfloat16, wmma::row_major> bh[4], bl[4];
#pragma unroll
            for (int i = 0; i < 2; i++) {
                wmma::load_matrix_sync(ah[i], &sAhi[wm * 32 + i * 16][kk], 40);
                wmma::load_matrix_sync(al[i], &sAlo[wm * 32 + i * 16][kk], 40);
            }
#pragma unroll
            for (int j = 0; j < 4; j++) {
                wmma::load_matrix_sync(bh[j], &sBhi[kk][wn * 64 + j * 16], 136);
                wmma::load_matrix_sync(bl[j], &sBlo[kk][wn * 64 + j * 16], 136);
            }
#pragma unroll
            for (int i = 0; i < 2; i++)
#pragma unroll
                for (int j = 0; j < 4; j++) {
                    wmma::mma_sync(acc[i][j], ah[i], bh[j], acc[i][j]);
                    wmma::mma_sync(acc[i][j], ah[i], bl[j], acc[i][j]);
                    wmma::mma_sync(acc[i][j], al[i], bh[j], acc[i][j]);
                }
        }
    }

    if (mode == 0) {
        float (*stage)[16] = (float (*)[16])(sMulti + wid * 256);
        __syncthreads();
#pragma unroll
        for (int i = 0; i < 2; i++)
#pragma unroll
            for (int j = 0; j < 4; j++) {
                for (int e = 0; e < acc[i][j].num_elements; e++)
                    acc[i][j].x[e] = fmaxf(acc[i][j].x[e], 0.f);
                wmma::store_matrix_sync(&stage[0][0], acc[i][j], 16, wmma::mem_row_major);
                __syncwarp();
                int r = lane & 15, c8 = (lane >> 4) * 8;
                size_t row = (size_t)(m0 + wm * 32 + i * 16 + r);
                size_t off = row * 1024 + (n0 + wn * 64 + j * 16 + c8);
                BF4 h0v, l0v, h1v, l1v;
#pragma unroll
                for (int e = 0; e < 4; e++) bsplit(stage[r][c8 + e],     h0v.v[e], l0v.v[e]);
#pragma unroll
                for (int e = 0; e < 4; e++) bsplit(stage[r][c8 + 4 + e], h1v.v[e], l1v.v[e]);
                *(BF4*)(Dhi + off)     = h0v;
                *(BF4*)(Dlo + off)     = l0v;
                *(BF4*)(Dhi + off + 4) = h1v;
                *(BF4*)(Dlo + off + 4) = l1v;
                __syncwarp();
            }
        return;
    }

#pragma unroll
    for (int i = 0; i < 2; i++)
#pragma unroll
        for (int j = 0; j < 4; j++) {
            int col = n0 + wn * 64 + j * 16;
            if (mode == 2) {
                int t = m0 >> 7;
                int b = wm * 32 + i * 16;
                float* p = D + (size_t)t * 1024 + (size_t)b * ((size_t)TN * 1024) + col;
                wmma::store_matrix_sync(p, acc[i][j], (unsigned)(TN * 1024), wmma::mem_row_major);
            } else {
                int row = m0 + wm * 32 + i * 16;
                wmma::store_matrix_sync(D + (size_t)row * N + col, acc[i][j], N, wmma::mem_row_major);
            }
        }
}

// ---------------- recurrent step kernel v2 ----------------
// 128 CTAs x 256 thr. CTA owns 32 permuted cols. K-chunk = 32, 3-buffer cp.async
// pipeline for H (hi+lo) and W (hi+lo) chunks. Conflict-free LDSM strides (40 bf16).
// SMEM: A bufs 3 x 20480B (hi[128][40] + lo[128][40]) | B bufs 3 x 5120B at +61440.
// z [128][36] fp32 overlays A buf region after the mainloop.
#define STP_ABUF 20480
#define STP_BOFF 61440
#define STP_BBUF 5120
#define STP_TOTAL (STP_BOFF + 3 * STP_BBUF)   // 76800

__device__ __forceinline__ void cp16(uint32_t dst, const void* src) {
    asm volatile("cp.async.cg.shared.global [%0], [%1], 16;" :: "r"(dst), "l"(src));
}
__device__ __forceinline__ void cp_commit() { asm volatile("cp.async.commit_group;"); }
template<int N> __device__ __forceinline__ void cp_wait() {
    asm volatile("cp.async.wait_group %0;" :: "n"(N));
}

__global__ __launch_bounds__(256, 1) void lstm_step2(
    const __nv_bfloat16* __restrict__ Wh_g, const __nv_bfloat16* __restrict__ Wl_g, int t)
{
    extern __shared__ char sm[];
    const uint32_t smb = (uint32_t)__cvta_generic_to_shared(sm);
    const int tid = threadIdx.x, wid = tid >> 5;
    const int bx = blockIdx.x;
    const int n0g = bx * 32;
    const int wm = wid >> 1, wn = wid & 1;

    const __nv_bfloat16* __restrict__ Hhi = g_Hhi + (size_t)t * (BSZ * UN);
    const __nv_bfloat16* __restrict__ Hlo = g_Hlo + (size_t)t * (BSZ * UN);

    // per-thread cp.async mapping
    const int arow = tid >> 1, aseg = (tid & 1) * 16;          // A: 2x cp16 hi, 2x lo
    const int brow = (tid & 127) >> 2, bseg = (tid & 3) * 8;   // B: 1 cp16 (hi if tid<128)
    const int bislo = tid >> 7;

    auto issue = [&](int chunk) {
        int buf = chunk % 3;
        uint32_t aB = smb + buf * STP_ABUF;
        uint32_t bB = smb + STP_BOFF + buf * STP_BBUF;
        const __nv_bfloat16* sh = Hhi + (size_t)arow * 1024 + chunk * 32 + aseg;
        const __nv_bfloat16* sl = Hlo + (size_t)arow * 1024 + chunk * 32 + aseg;
        uint32_t ad = aB + (uint32_t)(arow * 40 + aseg) * 2;
        cp16(ad,          sh);
        cp16(ad + 16,     sh + 8);
        cp16(ad + 10240,      sl);
        cp16(ad + 10240 + 16, sl + 8);
        const __nv_bfloat16* wsrc = (bislo ? Wl_g : Wh_g) +
            (size_t)(chunk * 32 + brow) * 4096 + n0g + bseg;
        cp16(bB + bislo * 2560 + (uint32_t)(brow * 40 + bseg) * 2, wsrc);
        cp_commit();
    };

    wmma::fragment<wmma::accumulator, 16, 16, 16, float> acc[2];
    wmma::fill_fragment(acc[0], 0.f);
    wmma::fill_fragment(acc[1], 0.f);

    issue(0);
    issue(1);

    for (int c = 0; c < 32; c++) {
        if (c < 31) cp_wait<1>(); else cp_wait<0>();
        __syncthreads();
        if (c + 2 < 32) issue(c + 2);

        int buf = c % 3;
        __nv_bfloat16 (*Ah)[40] = (__nv_bfloat16 (*)[40])(sm + buf * STP_ABUF);
        __nv_bfloat16 (*Al)[40] = (__nv_bfloat16 (*)[40])(sm + buf * STP_ABUF + 10240);
        __nv_bfloat16 (*Bh)[40] = (__nv_bfloat16 (*)[40])(sm + STP_BOFF + buf * STP_BBUF);
        __nv_bfloat16 (*Bl)[40] = (__nv_bfloat16 (*)[40])(sm + STP_BOFF + buf * STP_BBUF + 2560);

#pragma unroll
        for (int s = 0; s < 2; s++) {
            int kk = s * 16;
            wmma::fragment<wmma::matrix_a, 16, 16, 16, __nv_bfloat16, wmma::row_major> ah0, ah1, al0, al1;
            wmma::fragment<wmma::matrix_b, 16, 16, 16, __nv_bfloat16, wmma::row_major> bh, bl;
            wmma::load_matrix_sync(bh, &Bh[kk][wn * 16], 40);
            wmma::load_matrix_sync(bl, &Bl[kk][wn * 16], 40);
            wmma::load_matrix_sync(ah0, &Ah[wm * 32][kk], 40);
            wmma::load_matrix_sync(ah1, &Ah[wm * 32 + 16][kk], 40);
            wmma::load_matrix_sync(al0, &Al[wm * 32][kk], 40);
            wmma::load_matrix_sync(al1, &Al[wm * 32 + 16][kk], 40);
            wmma::mma_sync(acc[0], ah0, bh, acc[0]);
            wmma::mma_sync(acc[1], ah1, bh, acc[1]);
            wmma::mma_sync(acc[0], ah0, bl, acc[0]);
            wmma::mma_sync(acc[1], ah1, bl, acc[1]);
            wmma::mma_sync(acc[0], al0, bh, acc[0]);
            wmma::mma_sync(acc[1], al1, bh, acc[1]);
        }
    }

    // z overlay on A-buffer region
    __syncthreads();
    float (*z)[36] = (float (*)[36])sm;
    wmma::store_matrix_sync(&z[wm * 32][wn * 16],      acc[0], 36, wmma::mem_row_major);
    wmma::store_matrix_sync(&z[wm * 32 + 16][wn * 16], acc[1], 36, wmma::mem_row_major);
    __syncthreads();

    // gate epilogue: thread -> row m = tid&127, half = tid>>7 -> 4 units (16 perm cols)
    const int m = tid & 127;
    const int half = tid >> 7;
    const int pc = half * 16;
    const float* __restrict__ zk = g_ZK + ((size_t)t * BSZ + m) * 4096 + n0g + pc;
    float zkf[16];
#pragma unroll
    for (int q = 0; q < 4; q++) {
        float4 v = *(const float4*)(zk + q * 4);
        zkf[q * 4 + 0] = v.x; zkf[q * 4 + 1] = v.y;
        zkf[q * 4 + 2] = v.z; zkf[q * 4 + 3] = v.w;
    }
    float* __restrict__ cptr = g_C + (size_t)m * UN + bx * 8 + half * 4;
    float4 cv4 = *(const float4*)cptr;
    float cv[4] = {cv4.x, cv4.y, cv4.z, cv4.w};
    BF4 hh, hl;
#pragma unroll
    for (int e = 0; e < 4; e++) {
        float zi = z[m][pc + e * 4 + 0] + zkf[e * 4 + 0];
        float zf = z[m][pc + e * 4 + 1] + zkf[e * 4 + 1];
        float zg = z[m][pc + e * 4 + 2] + zkf[e * 4 + 2];
        float zo = z[m][pc + e * 4 + 3] + zkf[e * 4 + 3];
        float si = 1.f / (1.f + __expf(-zi));
        float sf = 1.f / (1.f + __expf(-zf));
        float so = 1.f / (1.f + __expf(-zo));
        float cn = sf * cv[e] + si * tanhf(zg);
        float hn = so * tanhf(cn);
        cv[e] = cn;
        bsplit(hn, hh.v[e], hl.v[e]);
    }
    *(float4*)cptr = make_float4(cv[0], cv[1], cv[2], cv[3]);
    size_t ho = (size_t)(t + 1) * (BSZ * UN) + (size_t)m * UN + bx * 8 + half * 4;
    *(BF4*)(g_Hhi + ho) = hh;
    *(BF4*)(g_Hlo + ho) = hl;
}

// ---------------- host ----------------
extern "C" void kernel_launch(void* const* d_in, const int* in_sizes, int n_in,
                              void* d_out, int out_size)
{
    const float* h0    = (const float*)d_in[0];
    const float* c0    = (const float*)d_in[1];
    const float* X     = (const float*)d_in[2];
    const float* W_emb = (const float*)d_in[3];
    const float* b_emb = (const float*)d_in[4];
    const float* W_k   = (const float*)d_in[5];
    const float* W_r   = (const float*)d_in[6];
    const float* b_r   = (const float*)d_in[7];
    const float* W_out = (const float*)d_in[8];
    const float* b_out = (const float*)d_in[9];
    (void)in_sizes; (void)n_in; (void)out_size;

    __nv_bfloat16 *pXhi, *pXlo, *pEhi, *pElo, *pHhi, *pHlo;
    __nv_bfloat16 *pWembh, *pWembl, *pWouth, *pWoutl, *pWkh, *pWkl, *pWrh, *pWrl;
    float *pZK;
    cudaGetSymbolAddress((void**)&pXhi, g_Xhi);
    cudaGetSymbolAddress((void**)&pXlo, g_Xlo);
    cudaGetSymbolAddress((void**)&pEhi, g_Ehi);
    cudaGetSymbolAddress((void**)&pElo, g_Elo);
    cudaGetSymbolAddress((void**)&pHhi, g_Hhi);
    cudaGetSymbolAddress((void**)&pHlo, g_Hlo);
    cudaGetSymbolAddress((void**)&pWembh, g_Wemb_hi);
    cudaGetSymbolAddress((void**)&pWembl, g_Wemb_lo);
    cudaGetSymbolAddress((void**)&pWouth, g_Wout_hi);
    cudaGetSymbolAddress((void**)&pWoutl, g_Wout_lo);
    cudaGetSymbolAddress((void**)&pWkh, g_Wk_hi);
    cudaGetSymbolAddress((void**)&pWkl, g_Wk_lo);
    cudaGetSymbolAddress((void**)&pWrh, g_Wr_hi);
    cudaGetSymbolAddress((void**)&pWrl, g_Wr_lo);
    cudaGetSymbolAddress((void**)&pZK, g_ZK);

    cudaFuncSetAttribute(lstm_step2, cudaFuncAttributeMaxDynamicSharedMemorySize, STP_TOTAL);

    init_state<<<(BSZ * UN + 255) / 256, 256>>>(h0, c0);
    split_X<<<(int)((size_t)MROWS * UN / 4 / 256), 256>>>(X);
    split_W<<<(1024 * 1024 + 255) / 256, 256>>>(W_emb, pWembh, pWembl, 1024, 0);
    split_W<<<(1024 * 1024 + 255) / 256, 256>>>(W_out, pWouth, pWoutl, 1024, 0);
    split_W<<<(1024 * 4096 + 255) / 256, 256>>>(W_k, pWkh, pWkl, 4096, 1);
    split_W<<<(1024 * 4096 + 255) / 256, 256>>>(W_r, pWrh, pWrl, 4096, 1);

    {   // E = relu(X @ W_emb + b_emb), bf16 split written directly
        dim3 grid(1024 / 128, MROWS / 128);
        wgemm<<<grid, 256>>>(pXhi, pXlo, pWembh, pWembl, b_emb,
                             nullptr, pEhi, pElo, 1024, 0);
    }
    {   // ZK = E @ W_k + b_r (unit-major permuted columns)
        dim3 grid(4096 / 128, MROWS / 128);
        wgemm<<<grid, 256>>>(pEhi, pElo, pWkh, pWkl, b_r,
                             pZK, nullptr, nullptr, 4096, 1);
    }

    // recurrence: 512 per-step launches, pipelined step kernel
    for (int t = 0; t < TN; t++)
        lstm_step2<<<128, 256, STP_TOTAL>>>(pWrh, pWrl, t);

    {   // OUT = H @ W_out + b_out, scattered to [b][t][:]
        dim3 grid(1024 / 128, MROWS / 128);
        wgemm<<<grid, 256>>>(pHhi + (size_t)BSZ * UN, pHlo + (size_t)BSZ * UN,
                             pWouth, pWoutl, b_out,
                             (float*)d_out, nullptr, nullptr, 1024, 2);
    }
}